// round 10
// baseline (speedup 1.0000x reference)
#include <cuda_runtime.h>
#include <cuda_fp16.h>
#include <math.h>
#include <stdint.h>

#define HID 128
#define NB 32
#define TILE_M 128
#define MAX_NODES 50000
#define FULL 0xffffffffu

// strides in halves
#define WSTR 520          // weight row: 128 n * 4 halves + 8 pad
#define A1STR 304         // A1 row: 288 halves + 16 pad (conflict-free frag rows)
#define A2STR 136         // A2 row: 128 halves + 8 pad

// dynamic smem layout (byte offsets)
#define OFF_W1   0            // 72 * 520 * 2  = 74880
#define OFF_W2   74880        // 32 * 520 * 2  = 33280
#define OFF_A1   108160       // 128 * 304 * 2 = 77824
#define OFF_A2   185984       // 128 * 136 * 2 = 34816
#define OFF_SRC  220800       // 512
#define OFF_DST  221312       // 512
#define OFF_DIST 221824       // 512
#define OFF_B1   222336       // 512
#define OFF_B2   222848       // 512
#define SMEM_DYN 223360

// ---------------- device scratch ----------------
__device__ float  g_acc[(size_t)MAX_NODES * HID];
__device__ float  g_deg[MAX_NODES];
__device__ __half g_W1h[72 * 512];   // [ks*4+tig][n*4+j], k = ks*16 + 2*tig + (j&1) + 8*(j>>1)
__device__ __half g_W2h[32 * 512];
__device__ float  g_Woi[HID * HID];  // pair-interleaved for node kernel

#define MMA_F16(C, a0, a1, a2, a3, b0, b1) \
    asm volatile("mma.sync.aligned.m16n8k16.row.col.f32.f16.f16.f32 " \
        "{%0,%1,%2,%3}, {%4,%5,%6,%7}, {%8,%9}, {%0,%1,%2,%3};" \
        : "+f"((C)[0]), "+f"((C)[1]), "+f"((C)[2]), "+f"((C)[3]) \
        : "r"(a0), "r"(a1), "r"(a2), "r"(a3), "r"(b0), "r"(b1))

__device__ __forceinline__ void red_add_v4(float* addr, float a, float b, float c, float d) {
    asm volatile("red.global.add.v4.f32 [%0], {%1,%2,%3,%4};"
                 :: "l"(addr), "f"(a), "f"(b), "f"(c), "f"(d) : "memory");
}
__device__ __forceinline__ uint32_t h2u(__half2 h) { return *reinterpret_cast<uint32_t*>(&h); }

// ---------------- small kernels ----------------
__global__ void zero_kernel(int n_nodes) {
    int tid = blockIdx.x * blockDim.x + threadIdx.x;
    int stride = gridDim.x * blockDim.x;
    int tot4 = (n_nodes * HID) / 4;
    float4 z = make_float4(0.f, 0.f, 0.f, 0.f);
    float4* p = (float4*)g_acc;
    for (int i = tid; i < tot4; i += stride) p[i] = z;
    for (int i = tid; i < n_nodes; i += stride) g_deg[i] = 0.0f;
}

__global__ void prep_kernel(const float* __restrict__ W1, const float* __restrict__ W2,
                            const float* __restrict__ Wo) {
    int tid = blockIdx.x * blockDim.x + threadIdx.x;
    int stride = gridDim.x * blockDim.x;
    for (int i = tid; i < 72 * 512; i += stride) {
        int row = i >> 9, r = i & 511;
        int n = r >> 2, j = r & 3;
        int k = (row >> 2) * 16 + 2 * (row & 3) + (j & 1) + 8 * (j >> 1);
        g_W1h[i] = __float2half(W1[(size_t)k * HID + n]);
    }
    for (int i = tid; i < 32 * 512; i += stride) {
        int row = i >> 9, r = i & 511;
        int n = r >> 2, j = r & 3;
        int k = (row >> 2) * 16 + 2 * (row & 3) + (j & 1) + 8 * (j >> 1);
        g_W2h[i] = __float2half(W2[(size_t)k * HID + n]);
    }
    for (int i = tid; i < HID * HID; i += stride) {
        int kp = i / (2 * HID);
        int r = i % (2 * HID);
        int cc = r >> 1, j = r & 1;
        g_Woi[i] = Wo[(size_t)(2 * kp + j) * HID + cc];
    }
}

// ---------------- edge kernel: persistent, 512 thr, single-phase staging ----------------
__global__ __launch_bounds__(512, 1)
void edge_kernel(const float* __restrict__ feat, const float* __restrict__ pos,
                 const int* __restrict__ ei, const float* __restrict__ b1,
                 const float* __restrict__ b2, int E)
{
    extern __shared__ char smc[];
    __half* smW1 = (__half*)(smc + OFF_W1);     // [72][520]
    __half* smW2 = (__half*)(smc + OFF_W2);     // [32][520]
    __half* smA1 = (__half*)(smc + OFF_A1);     // [128][304]
    __half* smA2 = (__half*)(smc + OFF_A2);     // [128][136]
    int*    sSrc = (int*)(smc + OFF_SRC);
    int*    sDst = (int*)(smc + OFF_DST);
    float*  sDist = (float*)(smc + OFF_DIST);
    float*  sB1  = (float*)(smc + OFF_B1);
    float*  sB2  = (float*)(smc + OFF_B2);

    const int tid = threadIdx.x;
    const int wid = tid >> 5, lane = tid & 31;
    const int mg = wid >> 2, nq = wid & 3;       // warp tile: rows mg*32..+31, cols nq*32..+31
    const int gid = lane >> 2, tig = lane & 3;
    const int m = tid >> 2, q = tid & 3;         // staging: edge row m, quarter q

    // resident weights (compact global -> padded smem rows)
    for (int i = tid; i < 72 * 64; i += 512) {
        int row = i >> 6, c4 = i & 63;
        *((uint4*)(smW1 + row * WSTR) + c4) = ((const uint4*)g_W1h)[i];
    }
    for (int i = tid; i < 32 * 64; i += 512) {
        int row = i >> 6, c4 = i & 63;
        *((uint4*)(smW2 + row * WSTR) + c4) = ((const uint4*)g_W2h)[i];
    }
    if (tid < HID) { sB1[tid] = b1[tid]; sB2[tid] = b2[tid]; }

    const int ntiles = (E + TILE_M - 1) / TILE_M;
    const float step = 5.0f / (float)(NB - 1);
    const float invw = 1.0f / (0.5f * (step + 0.01f));

    for (int t = blockIdx.x; t < ntiles; t += gridDim.x) {
        const int ebase = t * TILE_M;
        __syncthreads();   // protect meta/A1/A2 against previous-tile readers

        if (tid < TILE_M) {
            int e = ebase + tid;
            int s = 0, d = 0; float dist = 0.0f;
            if (e < E) {
                s = ei[e]; d = ei[E + e];
                float dx = pos[3*d+0] - pos[3*s+0];
                float dy = pos[3*d+1] - pos[3*s+1];
                float dz = pos[3*d+2] - pos[3*s+2];
                dist = fminf(sqrtf(dx*dx + dy*dy + dz*dz), 5.0f);
                atomicAdd(&g_deg[d], 1.0f);
            }
            sSrc[tid] = s; sDst[tid] = d; sDist[tid] = dist;
        }
        __syncthreads();

        // ---------- stage FULL A1 [128][288] fp16, one phase ----------
        {
            int node = (q < 2) ? sSrc[m] : sDst[m];
            const float4* p = (const float4*)(feat + (size_t)node * HID + (q & 1) * 64);
            __half* arow = smA1 + m * A1STR;
            #pragma unroll
            for (int t4 = 0; t4 < 4; t4++) {
                float4 x0 = __ldg(p + t4*4 + 0);
                float4 x1 = __ldg(p + t4*4 + 1);
                float4 x2 = __ldg(p + t4*4 + 2);
                float4 x3 = __ldg(p + t4*4 + 3);
                float f[16] = {x0.x,x0.y,x0.z,x0.w, x1.x,x1.y,x1.z,x1.w,
                               x2.x,x2.y,x2.z,x2.w, x3.x,x3.y,x3.z,x3.w};
                __half* kbase = arow + (q * 4 + t4) * 16;
                #pragma unroll
                for (int t2 = 0; t2 < 4; t2++) {
                    uint2 u;
                    u.x = h2u(__floats2half2_rn(f[2*t2],     f[2*t2 + 1]));
                    u.y = h2u(__floats2half2_rn(f[2*t2 + 8], f[2*t2 + 9]));
                    *(uint2*)(kbase + t2 * 4) = u;
                }
            }
            // rbf: this thread covers basis indices q*8 .. q*8+7
            float dist = sDist[m];
            int qp = q & 1;
            __half* kbase = arow + (16 + (q >> 1)) * 16;
            #pragma unroll
            for (int t2 = 0; t2 < 4; t2++) {
                int j0 = q * 8 + 2 * t2;
                float t0 = (dist - (float)j0 * step) * invw;
                float t1 = (dist - (float)(j0 + 1) * step) * invw;
                float e0 = __expf(-0.5f * t0 * t0);
                float e1 = __expf(-0.5f * t1 * t1);
                *(__half2*)(kbase + t2 * 4 + 2 * qp) = __floats2half2_rn(e0, e1);
            }
        }
        __syncthreads();

        // ---------- layer 1: single pass, 18 k-steps ----------
        float c1f[2][4][4];
        #pragma unroll
        for (int a = 0; a < 2; a++)
            #pragma unroll
            for (int b = 0; b < 4; b++)
                #pragma unroll
                for (int c = 0; c < 4; c++) c1f[a][b][c] = 0.0f;

        #pragma unroll
        for (int ks = 0; ks < 18; ks++) {
            uint2 a0 = *(const uint2*)(smA1 + (mg*32 + gid     ) * A1STR + ks*16 + tig*4);
            uint2 a1 = *(const uint2*)(smA1 + (mg*32 + gid +  8) * A1STR + ks*16 + tig*4);
            uint2 a2 = *(const uint2*)(smA1 + (mg*32 + gid + 16) * A1STR + ks*16 + tig*4);
            uint2 a3 = *(const uint2*)(smA1 + (mg*32 + gid + 24) * A1STR + ks*16 + tig*4);
            const __half* wrow = smW1 + (ks*4 + tig) * WSTR;
            #pragma unroll
            for (int nt = 0; nt < 4; nt++) {
                uint2 b = *(const uint2*)(wrow + (nq*32 + nt*8 + gid) * 4);
                MMA_F16(c1f[0][nt], a0.x, a1.x, a0.y, a1.y, b.x, b.y);
                MMA_F16(c1f[1][nt], a2.x, a3.x, a2.y, a3.y, b.x, b.y);
            }
        }

        // ---------- SiLU -> stage A2 [128][128] fp16 ----------
        #pragma unroll
        for (int mt = 0; mt < 2; mt++) {
            int row0 = mg*32 + mt*16 + gid;
            #pragma unroll
            for (int nt = 0; nt < 4; nt++) {
                const float* C = c1f[mt][nt];
                int c0 = nq*32 + nt*8 + 2*tig;
                int s  = c0 >> 4, kk = c0 & 15;
                int off = s*16 + ((kk & 7) >> 1) * 4 + (kk >> 3) * 2;
                float b1a = sB1[c0], b1b = sB1[c0 + 1];
                float v0 = C[0] + b1a, v1 = C[1] + b1b;
                float v2 = C[2] + b1a, v3 = C[3] + b1b;
                v0 = __fdividef(v0, 1.0f + __expf(-v0));
                v1 = __fdividef(v1, 1.0f + __expf(-v1));
                v2 = __fdividef(v2, 1.0f + __expf(-v2));
                v3 = __fdividef(v3, 1.0f + __expf(-v3));
                *(__half2*)(smA2 + row0 * A2STR + off)       = __floats2half2_rn(v0, v1);
                *(__half2*)(smA2 + (row0 + 8) * A2STR + off) = __floats2half2_rn(v2, v3);
            }
        }
        __syncthreads();

        // ---------- layer 2: single pass, 8 k-steps ----------
        float c2f[2][4][4];
        #pragma unroll
        for (int a = 0; a < 2; a++)
            #pragma unroll
            for (int b = 0; b < 4; b++)
                #pragma unroll
                for (int c = 0; c < 4; c++) c2f[a][b][c] = 0.0f;

        #pragma unroll
        for (int s = 0; s < 8; s++) {
            uint2 a0 = *(const uint2*)(smA2 + (mg*32 + gid     ) * A2STR + s*16 + tig*4);
            uint2 a1 = *(const uint2*)(smA2 + (mg*32 + gid +  8) * A2STR + s*16 + tig*4);
            uint2 a2 = *(const uint2*)(smA2 + (mg*32 + gid + 16) * A2STR + s*16 + tig*4);
            uint2 a3 = *(const uint2*)(smA2 + (mg*32 + gid + 24) * A2STR + s*16 + tig*4);
            const __half* wrow = smW2 + (s*4 + tig) * WSTR;
            #pragma unroll
            for (int nt = 0; nt < 4; nt++) {
                uint2 b = *(const uint2*)(wrow + (nq*32 + nt*8 + gid) * 4);
                MMA_F16(c2f[0][nt], a0.x, a1.x, a0.y, a1.y, b.x, b.y);
                MMA_F16(c2f[1][nt], a2.x, a3.x, a2.y, a3.y, b.x, b.y);
            }
        }

        // ---------- epilogue: +b2, pair lanes, vector red scatter ----------
        #pragma unroll
        for (int mt = 0; mt < 2; mt++) {
            int r0 = mg*32 + mt*16 + gid;
            int r1 = r0 + 8;
            int d0 = sDst[r0], d1 = sDst[r1];
            bool ok0 = (ebase + r0) < E, ok1 = (ebase + r1) < E;
            #pragma unroll
            for (int nt = 0; nt < 4; nt++) {
                float* C = c2f[mt][nt];
                float q0 = __shfl_xor_sync(FULL, C[0], 1);
                float q1 = __shfl_xor_sync(FULL, C[1], 1);
                float q2 = __shfl_xor_sync(FULL, C[2], 1);
                float q3 = __shfl_xor_sync(FULL, C[3], 1);
                if ((tig & 1) == 0) {
                    int cb = nq*32 + nt*8 + 2*tig;
                    float4 bb = *(const float4*)(sB2 + cb);
                    if (ok0)
                        red_add_v4(g_acc + (size_t)d0 * HID + cb,
                                   C[0] + bb.x, C[1] + bb.y, q0 + bb.z, q1 + bb.w);
                } else {
                    int cb = nq*32 + nt*8 + 2*(tig - 1);
                    float4 bb = *(const float4*)(sB2 + cb);
                    if (ok1)
                        red_add_v4(g_acc + (size_t)d1 * HID + cb,
                                   q2 + bb.x, q3 + bb.y, C[2] + bb.z, C[3] + bb.w);
                }
            }
        }
    }
}

// ---------------- node output GEMM (validated, fp32) ----------------
__device__ __forceinline__ void ffma2(unsigned long long& d, unsigned long long a, unsigned long long b) {
    asm("fma.rn.f32x2 %0, %1, %2, %0;" : "+l"(d) : "l"(a), "l"(b));
}
__device__ __forceinline__ float hsum2(unsigned long long v) {
    float2 f = *reinterpret_cast<float2*>(&v);
    return f.x + f.y;
}

__global__ __launch_bounds__(128)
void node_kernel(const float* __restrict__ bo, float* __restrict__ out, int n_nodes)
{
    __shared__ float smem[4][8][HID];
    const int warp = threadIdx.x >> 5;
    const int lane = threadIdx.x & 31;
    const int nbase = blockIdx.x * 32 + warp * 8;
    float (*x)[HID] = smem[warp];

    float my_inv = 1.0f;
    if (lane < 8) {
        int n = nbase + lane;
        if (n < n_nodes) my_inv = 1.0f / fmaxf(g_deg[n], 1.0f);
    }
    #pragma unroll
    for (int e = 0; e < 8; e++) {
        float inv = __shfl_sync(FULL, my_inv, e);
        int n = nbase + e;
        float4 a = make_float4(0.f, 0.f, 0.f, 0.f);
        if (n < n_nodes) a = *(const float4*)(g_acc + (size_t)n * HID + 4 * lane);
        a.x *= inv; a.y *= inv; a.z *= inv; a.w *= inv;
        *(float4*)(&x[e][4 * lane]) = a;
    }
    __syncwarp();

    unsigned long long acc[8][4];
    #pragma unroll
    for (int e = 0; e < 8; e++)
        #pragma unroll
        for (int c = 0; c < 4; c++) acc[e][c] = 0ull;

    #pragma unroll 4
    for (int kp = 0; kp < HID / 2; kp++) {
        const float* wrow = g_Woi + (size_t)kp * (2 * HID) + 8 * lane;
        ulonglong2 wA = *(const ulonglong2*)(wrow);
        ulonglong2 wB = *(const ulonglong2*)(wrow + 4);
        #pragma unroll
        for (int e = 0; e < 8; e++) {
            unsigned long long m2 = *(const unsigned long long*)(&x[e][2 * kp]);
            ffma2(acc[e][0], m2, wA.x);
            ffma2(acc[e][1], m2, wA.y);
            ffma2(acc[e][2], m2, wB.x);
            ffma2(acc[e][3], m2, wB.y);
        }
    }
    float4 bb = *(const float4*)(bo + 4 * lane);
    #pragma unroll
    for (int e = 0; e < 8; e++) {
        int n = nbase + e;
        if (n < n_nodes) {
            float4 o;
            o.x = hsum2(acc[e][0]) + bb.x;
            o.y = hsum2(acc[e][1]) + bb.y;
            o.z = hsum2(acc[e][2]) + bb.z;
            o.w = hsum2(acc[e][3]) + bb.w;
            *(float4*)(out + (size_t)n * HID + 4 * lane) = o;
        }
    }
}

// ---------------- launch ----------------
extern "C" void kernel_launch(void* const* d_in, const int* in_sizes, int n_in,
                              void* d_out, int out_size) {
    const float* feat = (const float*)d_in[0];
    const float* pos  = (const float*)d_in[1];
    const int*   ei   = (const int*)d_in[2];
    const float* W1   = (const float*)d_in[3];
    const float* b1   = (const float*)d_in[4];
    const float* W2   = (const float*)d_in[5];
    const float* b2   = (const float*)d_in[6];
    const float* Wo   = (const float*)d_in[7];
    const float* bo   = (const float*)d_in[8];

    int n_nodes = in_sizes[0] / HID;
    int E = in_sizes[2] / 2;

    (void)cudaFuncSetAttribute(edge_kernel, cudaFuncAttributeMaxDynamicSharedMemorySize, SMEM_DYN);

    zero_kernel<<<512, 256>>>(n_nodes);
    prep_kernel<<<64, 256>>>(W1, W2, Wo);
    edge_kernel<<<148, 512, SMEM_DYN>>>(feat, pos, ei, b1, b2, E);

    int nblocks = (n_nodes + 31) / 32;
    node_kernel<<<nblocks, 128>>>(bo, (float*)d_out, n_nodes);
}

// round 11
// speedup vs baseline: 1.5303x; 1.5303x over previous
#include <cuda_runtime.h>
#include <cuda_fp16.h>
#include <math.h>
#include <stdint.h>

#define HID 128
#define NB 32
#define TILE_M 128
#define MAX_NODES 50000
#define FULL 0xffffffffu

// strides in halves
#define WSTR 528          // weight row: 512 data + 16 pad  (264 words ≡ 8 mod 32: B-frags 2-txn)
#define A1STR 40          // A1 row: 32 data + 8 pad        (20 words ≡ 20 mod 32: A-frags 2-txn)
#define A2STR 168         // A2 row: 128 data + 40 pad      (84 words ≡ 20 mod 32)
#define A1BUF (TILE_M * A1STR)

// dynamic smem layout (byte offsets)
#define OFF_W1   0            // 72 * 528 * 2  = 76032
#define OFF_W2   76032        // 32 * 528 * 2  = 33792
#define OFF_A1   109824       // 2 * 128*40*2  = 20480
#define OFF_A2   130304       // 128 * 168 * 2 = 43008
#define OFF_SRC  173312       // 512
#define OFF_DST  173824       // 512
#define OFF_DIST 174336       // 512
#define OFF_B1   174848       // 512
#define OFF_B2   175360       // 512
#define SMEM_DYN 175872

// ---------------- device scratch ----------------
__device__ float  g_acc[(size_t)MAX_NODES * HID];
__device__ float  g_deg[MAX_NODES];
__device__ __half g_W1h[72 * 512];   // [ks*4+tig][n*4+j], k = ks*16 + 2*tig + (j&1) + 8*(j>>1)
__device__ __half g_W2h[32 * 512];
__device__ float  g_Woi[HID * HID];  // pair-interleaved for node kernel

#define MMA_F16(C, a0, a1, a2, a3, b0, b1) \
    asm volatile("mma.sync.aligned.m16n8k16.row.col.f32.f16.f16.f32 " \
        "{%0,%1,%2,%3}, {%4,%5,%6,%7}, {%8,%9}, {%0,%1,%2,%3};" \
        : "+f"((C)[0]), "+f"((C)[1]), "+f"((C)[2]), "+f"((C)[3]) \
        : "r"(a0), "r"(a1), "r"(a2), "r"(a3), "r"(b0), "r"(b1))

__device__ __forceinline__ void red_add_v4(float* addr, float a, float b, float c, float d) {
    asm volatile("red.global.add.v4.f32 [%0], {%1,%2,%3,%4};"
                 :: "l"(addr), "f"(a), "f"(b), "f"(c), "f"(d) : "memory");
}
__device__ __forceinline__ uint32_t h2u(__half2 h) { return *reinterpret_cast<uint32_t*>(&h); }

// ---------------- small kernels ----------------
__global__ void zero_kernel(int n_nodes) {
    int tid = blockIdx.x * blockDim.x + threadIdx.x;
    int stride = gridDim.x * blockDim.x;
    int tot4 = (n_nodes * HID) / 4;
    float4 z = make_float4(0.f, 0.f, 0.f, 0.f);
    float4* p = (float4*)g_acc;
    for (int i = tid; i < tot4; i += stride) p[i] = z;
    for (int i = tid; i < n_nodes; i += stride) g_deg[i] = 0.0f;
}

__global__ void prep_kernel(const float* __restrict__ W1, const float* __restrict__ W2,
                            const float* __restrict__ Wo) {
    int tid = blockIdx.x * blockDim.x + threadIdx.x;
    int stride = gridDim.x * blockDim.x;
    for (int i = tid; i < 72 * 512; i += stride) {
        int row = i >> 9, r = i & 511;
        int n = r >> 2, j = r & 3;
        int k = (row >> 2) * 16 + 2 * (row & 3) + (j & 1) + 8 * (j >> 1);
        g_W1h[i] = __float2half(W1[(size_t)k * HID + n]);
    }
    for (int i = tid; i < 32 * 512; i += stride) {
        int row = i >> 9, r = i & 511;
        int n = r >> 2, j = r & 3;
        int k = (row >> 2) * 16 + 2 * (row & 3) + (j & 1) + 8 * (j >> 1);
        g_W2h[i] = __float2half(W2[(size_t)k * HID + n]);
    }
    for (int i = tid; i < HID * HID; i += stride) {
        int kp = i / (2 * HID);
        int r = i % (2 * HID);
        int cc = r >> 1, j = r & 1;
        g_Woi[i] = Wo[(size_t)(2 * kp + j) * HID + cc];
    }
}

// ---------------- edge kernel: persistent, 512 thr, chunk-pipelined ----------------
__global__ __launch_bounds__(512, 1)
void edge_kernel(const float* __restrict__ feat, const float* __restrict__ pos,
                 const int* __restrict__ ei, const float* __restrict__ b1,
                 const float* __restrict__ b2, int E)
{
    extern __shared__ char smc[];
    __half* smW1 = (__half*)(smc + OFF_W1);     // [72][528]
    __half* smW2 = (__half*)(smc + OFF_W2);     // [32][528]
    __half* smA1 = (__half*)(smc + OFF_A1);     // 2 x [128][40]
    __half* smA2 = (__half*)(smc + OFF_A2);     // [128][168]
    int*    sSrc = (int*)(smc + OFF_SRC);
    int*    sDst = (int*)(smc + OFF_DST);
    float*  sDist = (float*)(smc + OFF_DIST);
    float*  sB1  = (float*)(smc + OFF_B1);
    float*  sB2  = (float*)(smc + OFF_B2);

    const int tid = threadIdx.x;
    const int wid = tid >> 5, lane = tid & 31;
    const int mg = wid >> 2, nq = wid & 3;       // warp tile: rows mg*32..+31, cols nq*32..+31
    const int gid = lane >> 2, tig = lane & 3;
    const int m = tid >> 2, q = tid & 3;         // staging: edge row m, k-eighth q (8 values)
    const int sks = q >> 1, sh = q & 1;          // staging kstep within chunk, half

    // resident weights (compact global -> padded smem rows)
    for (int i = tid; i < 72 * 64; i += 512) {
        int row = i >> 6, c4 = i & 63;
        *((uint4*)(smW1 + row * WSTR) + c4) = ((const uint4*)g_W1h)[i];
    }
    for (int i = tid; i < 32 * 64; i += 512) {
        int row = i >> 6, c4 = i & 63;
        *((uint4*)(smW2 + row * WSTR) + c4) = ((const uint4*)g_W2h)[i];
    }
    if (tid < HID) { sB1[tid] = b1[tid]; sB2[tid] = b2[tid]; }

    const int ntiles = (E + TILE_M - 1) / TILE_M;
    const float step = 5.0f / (float)(NB - 1);
    const float invw = 1.0f / (0.5f * (step + 0.01f));

    for (int t = blockIdx.x; t < ntiles; t += gridDim.x) {
        const int ebase = t * TILE_M;
        __syncthreads();   // protect meta/A2 against previous-tile readers

        if (tid < TILE_M) {
            int e = ebase + tid;
            int s = 0, d = 0; float dist = 0.0f;
            if (e < E) {
                s = ei[e]; d = ei[E + e];
                float dx = pos[3*d+0] - pos[3*s+0];
                float dy = pos[3*d+1] - pos[3*s+1];
                float dz = pos[3*d+2] - pos[3*s+2];
                dist = fminf(sqrtf(dx*dx + dy*dy + dz*dz), 5.0f);
                atomicAdd(&g_deg[d], 1.0f);
            }
            sSrc[tid] = s; sDst[tid] = d; sDist[tid] = dist;
        }
        __syncthreads();

        float c1f[2][4][4];
        #pragma unroll
        for (int a = 0; a < 2; a++)
            #pragma unroll
            for (int b = 0; b < 4; b++)
                #pragma unroll
                for (int c = 0; c < 4; c++) c1f[a][b][c] = 0.0f;

        // prefetch chunk 0: this thread's 8 floats (src feats, cols q*8..q*8+7)
        float vv[8];
        {
            int node = sSrc[m];
            const float4* p = (const float4*)(feat + (size_t)node * HID + q * 8);
            float4 x0 = __ldg(p), x1 = __ldg(p + 1);
            vv[0]=x0.x; vv[1]=x0.y; vv[2]=x0.z; vv[3]=x0.w;
            vv[4]=x1.x; vv[5]=x1.y; vv[6]=x1.z; vv[7]=x1.w;
        }

        // ---------- layer 1: 9 chunks of k=32, double-buffered, 1 sync/chunk ----------
        #pragma unroll
        for (int c = 0; c < 9; c++) {
            {   // store vv (chunk c) into buffer c&1, permuted fp16 layout
                // k-offset kk = 8*sh + j maps to pos (j>>1)*4 + 2*sh + (j&1) in kstep group sks
                __half* kbase = smA1 + (c & 1) * A1BUF + m * A1STR + sks * 16 + 2 * sh;
                #pragma unroll
                for (int j2 = 0; j2 < 4; j2++)
                    *(__half2*)(kbase + j2 * 4) = __floats2half2_rn(vv[2*j2], vv[2*j2 + 1]);
            }
            __syncthreads();

            // prefetch next chunk during mma
            float vn[8];
            if (c < 8) {
                if (c < 7) {
                    int node = ((c + 1) < 4) ? sSrc[m] : sDst[m];
                    const float4* p = (const float4*)(feat + (size_t)node * HID + ((c+1) & 3) * 32 + q * 8);
                    float4 x0 = __ldg(p), x1 = __ldg(p + 1);
                    vn[0]=x0.x; vn[1]=x0.y; vn[2]=x0.z; vn[3]=x0.w;
                    vn[4]=x1.x; vn[5]=x1.y; vn[6]=x1.z; vn[7]=x1.w;
                } else {
                    float dist = sDist[m];
                    #pragma unroll
                    for (int i = 0; i < 8; i++) {
                        float tt = (dist - (float)(q*8 + i) * step) * invw;
                        vn[i] = __expf(-0.5f * tt * tt);
                    }
                }
            }

            const __half* Ab = smA1 + (c & 1) * A1BUF;
            #pragma unroll
            for (int s = 0; s < 2; s++) {
                uint2 a0 = *(const uint2*)(Ab + (mg*32 + gid     ) * A1STR + s*16 + tig*4);
                uint2 a1 = *(const uint2*)(Ab + (mg*32 + gid +  8) * A1STR + s*16 + tig*4);
                uint2 a2 = *(const uint2*)(Ab + (mg*32 + gid + 16) * A1STR + s*16 + tig*4);
                uint2 a3 = *(const uint2*)(Ab + (mg*32 + gid + 24) * A1STR + s*16 + tig*4);
                const __half* wrow = smW1 + ((c*2 + s)*4 + tig) * WSTR;
                #pragma unroll
                for (int nt = 0; nt < 4; nt++) {
                    uint2 b = *(const uint2*)(wrow + (nq*32 + nt*8 + gid) * 4);
                    MMA_F16(c1f[0][nt], a0.x, a1.x, a0.y, a1.y, b.x, b.y);
                    MMA_F16(c1f[1][nt], a2.x, a3.x, a2.y, a3.y, b.x, b.y);
                }
            }
            if (c < 8) {
                #pragma unroll
                for (int i = 0; i < 8; i++) vv[i] = vn[i];
            }
        }

        // ---------- SiLU -> stage A2 [128][128] fp16 ----------
        #pragma unroll
        for (int mt = 0; mt < 2; mt++) {
            int row0 = mg*32 + mt*16 + gid;
            #pragma unroll
            for (int nt = 0; nt < 4; nt++) {
                const float* C = c1f[mt][nt];
                int c0 = nq*32 + nt*8 + 2*tig;
                int s  = c0 >> 4, kk = c0 & 15;
                int off = s*16 + ((kk & 7) >> 1) * 4 + (kk >> 3) * 2;
                float b1a = sB1[c0], b1b = sB1[c0 + 1];
                float v0 = C[0] + b1a, v1 = C[1] + b1b;
                float v2 = C[2] + b1a, v3 = C[3] + b1b;
                v0 = __fdividef(v0, 1.0f + __expf(-v0));
                v1 = __fdividef(v1, 1.0f + __expf(-v1));
                v2 = __fdividef(v2, 1.0f + __expf(-v2));
                v3 = __fdividef(v3, 1.0f + __expf(-v3));
                *(__half2*)(smA2 + row0 * A2STR + off)       = __floats2half2_rn(v0, v1);
                *(__half2*)(smA2 + (row0 + 8) * A2STR + off) = __floats2half2_rn(v2, v3);
            }
        }
        __syncthreads();

        // ---------- layer 2: single pass, 8 k-steps ----------
        float c2f[2][4][4];
        #pragma unroll
        for (int a = 0; a < 2; a++)
            #pragma unroll
            for (int b = 0; b < 4; b++)
                #pragma unroll
                for (int c = 0; c < 4; c++) c2f[a][b][c] = 0.0f;

        #pragma unroll
        for (int s = 0; s < 8; s++) {
            uint2 a0 = *(const uint2*)(smA2 + (mg*32 + gid     ) * A2STR + s*16 + tig*4);
            uint2 a1 = *(const uint2*)(smA2 + (mg*32 + gid +  8) * A2STR + s*16 + tig*4);
            uint2 a2 = *(const uint2*)(smA2 + (mg*32 + gid + 16) * A2STR + s*16 + tig*4);
            uint2 a3 = *(const uint2*)(smA2 + (mg*32 + gid + 24) * A2STR + s*16 + tig*4);
            const __half* wrow = smW2 + (s*4 + tig) * WSTR;
            #pragma unroll
            for (int nt = 0; nt < 4; nt++) {
                uint2 b = *(const uint2*)(wrow + (nq*32 + nt*8 + gid) * 4);
                MMA_F16(c2f[0][nt], a0.x, a1.x, a0.y, a1.y, b.x, b.y);
                MMA_F16(c2f[1][nt], a2.x, a3.x, a2.y, a3.y, b.x, b.y);
            }
        }

        // ---------- epilogue: +b2, pair lanes, vector red scatter ----------
        #pragma unroll
        for (int mt = 0; mt < 2; mt++) {
            int r0 = mg*32 + mt*16 + gid;
            int r1 = r0 + 8;
            int d0 = sDst[r0], d1 = sDst[r1];
            bool ok0 = (ebase + r0) < E, ok1 = (ebase + r1) < E;
            #pragma unroll
            for (int nt = 0; nt < 4; nt++) {
                float* C = c2f[mt][nt];
                float q0 = __shfl_xor_sync(FULL, C[0], 1);
                float q1 = __shfl_xor_sync(FULL, C[1], 1);
                float q2 = __shfl_xor_sync(FULL, C[2], 1);
                float q3 = __shfl_xor_sync(FULL, C[3], 1);
                if ((tig & 1) == 0) {
                    int cb = nq*32 + nt*8 + 2*tig;
                    float4 bb = *(const float4*)(sB2 + cb);
                    if (ok0)
                        red_add_v4(g_acc + (size_t)d0 * HID + cb,
                                   C[0] + bb.x, C[1] + bb.y, q0 + bb.z, q1 + bb.w);
                } else {
                    int cb = nq*32 + nt*8 + 2*(tig - 1);
                    float4 bb = *(const float4*)(sB2 + cb);
                    if (ok1)
                        red_add_v4(g_acc + (size_t)d1 * HID + cb,
                                   q2 + bb.x, q3 + bb.y, C[2] + bb.z, C[3] + bb.w);
                }
            }
        }
    }
}

// ---------------- node output GEMM (validated, fp32) ----------------
__device__ __forceinline__ void ffma2(unsigned long long& d, unsigned long long a, unsigned long long b) {
    asm("fma.rn.f32x2 %0, %1, %2, %0;" : "+l"(d) : "l"(a), "l"(b));
}
__device__ __forceinline__ float hsum2(unsigned long long v) {
    float2 f = *reinterpret_cast<float2*>(&v);
    return f.x + f.y;
}

__global__ __launch_bounds__(128)
void node_kernel(const float* __restrict__ bo, float* __restrict__ out, int n_nodes)
{
    __shared__ float smem[4][8][HID];
    const int warp = threadIdx.x >> 5;
    const int lane = threadIdx.x & 31;
    const int nbase = blockIdx.x * 32 + warp * 8;
    float (*x)[HID] = smem[warp];

    float my_inv = 1.0f;
    if (lane < 8) {
        int n = nbase + lane;
        if (n < n_nodes) my_inv = 1.0f / fmaxf(g_deg[n], 1.0f);
    }
    #pragma unroll
    for (int e = 0; e < 8; e++) {
        float inv = __shfl_sync(FULL, my_inv, e);
        int n = nbase + e;
        float4 a = make_float4(0.f, 0.f, 0.f, 0.f);
        if (n < n_nodes) a = *(const float4*)(g_acc + (size_t)n * HID + 4 * lane);
        a.x *= inv; a.y *= inv; a.z *= inv; a.w *= inv;
        *(float4*)(&x[e][4 * lane]) = a;
    }
    __syncwarp();

    unsigned long long acc[8][4];
    #pragma unroll
    for (int e = 0; e < 8; e++)
        #pragma unroll
        for (int c = 0; c < 4; c++) acc[e][c] = 0ull;

    #pragma unroll 4
    for (int kp = 0; kp < HID / 2; kp++) {
        const float* wrow = g_Woi + (size_t)kp * (2 * HID) + 8 * lane;
        ulonglong2 wA = *(const ulonglong2*)(wrow);
        ulonglong2 wB = *(const ulonglong2*)(wrow + 4);
        #pragma unroll
        for (int e = 0; e < 8; e++) {
            unsigned long long m2 = *(const unsigned long long*)(&x[e][2 * kp]);
            ffma2(acc[e][0], m2, wA.x);
            ffma2(acc[e][1], m2, wA.y);
            ffma2(acc[e][2], m2, wB.x);
            ffma2(acc[e][3], m2, wB.y);
        }
    }
    float4 bb = *(const float4*)(bo + 4 * lane);
    #pragma unroll
    for (int e = 0; e < 8; e++) {
        int n = nbase + e;
        if (n < n_nodes) {
            float4 o;
            o.x = hsum2(acc[e][0]) + bb.x;
            o.y = hsum2(acc[e][1]) + bb.y;
            o.z = hsum2(acc[e][2]) + bb.z;
            o.w = hsum2(acc[e][3]) + bb.w;
            *(float4*)(out + (size_t)n * HID + 4 * lane) = o;
        }
    }
}

// ---------------- launch ----------------
extern "C" void kernel_launch(void* const* d_in, const int* in_sizes, int n_in,
                              void* d_out, int out_size) {
    const float* feat = (const float*)d_in[0];
    const float* pos  = (const float*)d_in[1];
    const int*   ei   = (const int*)d_in[2];
    const float* W1   = (const float*)d_in[3];
    const float* b1   = (const float*)d_in[4];
    const float* W2   = (const float*)d_in[5];
    const float* b2   = (const float*)d_in[6];
    const float* Wo   = (const float*)d_in[7];
    const float* bo   = (const float*)d_in[8];

    int n_nodes = in_sizes[0] / HID;
    int E = in_sizes[2] / 2;

    (void)cudaFuncSetAttribute(edge_kernel, cudaFuncAttributeMaxDynamicSharedMemorySize, SMEM_DYN);

    zero_kernel<<<512, 256>>>(n_nodes);
    prep_kernel<<<64, 256>>>(W1, W2, Wo);
    edge_kernel<<<148, 512, SMEM_DYN>>>(feat, pos, ei, b1, b2, E);

    int nblocks = (n_nodes + 31) / 32;
    node_kernel<<<nblocks, 128>>>(bo, (float*)d_out, n_nodes);
}